// round 11
// baseline (speedup 1.0000x reference)
#include <cuda_runtime.h>
#include <cuda_bf16.h>
#include <cstdint>
#include <cstring>

// MLP_Interpolate: 4x nearest upsample + 2-layer MLP.
// Base GEMM on tensor pipe via baseline-PTX mma.sync m16n8k16 bf16
// (3-term split Ah*Bh + Al*Bh + Ah*Bl, fp32 accum, residual ~1.5e-5 rel).
// 256 threads/CTA, occupancy 4 (64 regs) -> 32 warps/SM, single wave.
// Epilogue j-split (thread s owns rows j in {2s,2s+1}); tables in
// __constant__ (prep kernel + captured D2D memcpyToSymbol).

namespace {

typedef unsigned long long ull;

__device__ __forceinline__ ull pk(float lo, float hi) {
    ull r; asm("mov.b64 %0, {%1, %2};" : "=l"(r) : "f"(lo), "f"(hi)); return r;
}
__device__ __forceinline__ float2 upk(ull a) {
    float2 r; asm("mov.b64 {%0, %1}, %2;" : "=f"(r.x), "=f"(r.y) : "l"(a)); return r;
}
__device__ __forceinline__ ull fmax2p(ull a, ull b, ull c) {
    ull d; asm("fma.rn.f32x2 %0, %1, %2, %3;" : "=l"(d) : "l"(a), "l"(b), "l"(c)); return d;
}
__device__ __forceinline__ ull relu2(ull v) {
    float2 t = upk(v);
    return pk(fmaxf(t.x, 0.f), fmaxf(t.y, 0.f));
}
__device__ __forceinline__ uint32_t s2u(const void* p) {
    uint32_t a;
    asm("{ .reg .u64 t; cvta.to.shared.u64 t, %1; cvt.u32.u64 %0, t; }" : "=r"(a) : "l"(p));
    return a;
}
__device__ __forceinline__ void ldsm4(uint32_t addr, uint32_t& r0, uint32_t& r1,
                                      uint32_t& r2, uint32_t& r3) {
    asm volatile("ldmatrix.sync.aligned.m8n8.x4.shared.b16 {%0,%1,%2,%3}, [%4];"
                 : "=r"(r0), "=r"(r1), "=r"(r2), "=r"(r3) : "r"(addr));
}
__device__ __forceinline__ void mma16816(float* d, const uint32_t* a,
                                         uint32_t b0, uint32_t b1) {
    asm volatile(
        "mma.sync.aligned.m16n8k16.row.col.f32.bf16.bf16.f32 "
        "{%0,%1,%2,%3}, {%4,%5,%6,%7}, {%8,%9}, {%0,%1,%2,%3};"
        : "+f"(d[0]), "+f"(d[1]), "+f"(d[2]), "+f"(d[3])
        : "r"(a[0]), "r"(a[1]), "r"(a[2]), "r"(a[3]), "r"(b0), "r"(b1));
}

constexpr int Hh = 128, Wd = 128, HW = Hh * Wd, OUT = 512;
constexpr int BSTR = 68;   // base_s row stride (floats); 272 B, 16B-aligned

// ET[2i] = {u_i, v_i, b1_i, 0}; ET[2i+1] = {w2[i][0..2], 0}; ET[128] = b2
__constant__ float4 cET[129];
__device__   float4 gET[129];

// smem layout (bytes); base_s (128*68*4 = 34816) overlays A/B after MMA
constexpr int S_AHI = 0;            // X_hi  [128][64 bf16]  16384
constexpr int S_ALO = 16384;        // X_lo                  16384
constexpr int S_BHI = 32768;        // W1T_hi [64][64 bf16]   8192
constexpr int S_BLO = 40960;        // W1T_lo                 8192
constexpr int S_TOTAL = 49152;

// split 8 floats -> bf16-hi quad + bf16-lo quad
__device__ __forceinline__ void pack8(const float* v, uint4& qh, uint4& ql) {
    uint32_t H[4], L[4];
    #pragma unroll
    for (int p = 0; p < 4; p++) {
        uint32_t hp;
        asm("cvt.rn.bf16x2.f32 %0, %1, %2;" : "=r"(hp) : "f"(v[2*p+1]), "f"(v[2*p]));
        const float h0 = __uint_as_float(hp << 16);
        const float h1 = __uint_as_float(hp & 0xffff0000u);
        const float l0 = v[2*p]   - h0;
        const float l1 = v[2*p+1] - h1;
        uint32_t lp;
        asm("cvt.rn.bf16x2.f32 %0, %1, %2;" : "=r"(lp) : "f"(l1), "f"(l0));
        H[p] = hp; L[p] = lp;
    }
    qh = make_uint4(H[0], H[1], H[2], H[3]);
    ql = make_uint4(L[0], L[1], L[2], L[3]);
}

__global__ void prep_et(const float* __restrict__ W1, const float* __restrict__ b1,
                        const float* __restrict__ W2, const float* __restrict__ b2)
{
    const int c = threadIdx.x;   // 64 threads
    gET[2 * c]     = make_float4(W1[64 * 64 + c], W1[64 * 64 + 64 + c], b1[c], 0.f);
    gET[2 * c + 1] = make_float4(W2[c * 3 + 0], W2[c * 3 + 1], W2[c * 3 + 2], 0.f);
    if (c == 0) gET[128] = make_float4(b2[0], b2[1], b2[2], 0.f);
}

__global__ __launch_bounds__(256, 4)
void mlp_interp_mma(const float* __restrict__ x, const float* __restrict__ W1,
                    float* __restrict__ out)
{
    extern __shared__ char smem[];
    const uint32_t sb = s2u(smem);
    const int tid  = threadIdx.x;
    const int lane = tid & 31;
    const int wid  = tid >> 5;            // 0..7
    const int px   = tid >> 1;            // pixel 0..127
    const int s    = tid & 1;             // j-half
    const int cta  = blockIdx.x;          // 512: (b, h)
    const int h = cta & (Hh - 1);
    const int b = cta >> 7;

    // ---- stage A: thread (px, s) packs channels [32s, 32s+32) of pixel px ----
    {
        const float* xp = x + ((size_t)b * 64 + 32 * s) * HW + h * Wd + px;
        #pragma unroll
        for (int qq = 0; qq < 4; qq++) {
            float v[8];
            #pragma unroll
            for (int c = 0; c < 8; c++) v[c] = xp[(size_t)(8 * qq + c) * HW];
            uint4 qhv, qlv;
            pack8(v, qhv, qlv);
            const int q = 4 * s + qq;
            const uint32_t off = (uint32_t)px * 128 + (uint32_t)((q ^ (px & 7)) << 4);
            *(uint4*)(smem + S_AHI + off) = qhv;
            *(uint4*)(smem + S_ALO + off) = qlv;
        }
    }

    if (tid >= 128) {
        // ---- stage B: thread (i, s2) packs W1[32s2..32s2+32][i] ----
        const int t2 = tid - 128;
        const int i  = t2 >> 1;
        const int s2 = t2 & 1;
        #pragma unroll
        for (int qq = 0; qq < 4; qq++) {
            float v[8];
            #pragma unroll
            for (int c = 0; c < 8; c++) v[c] = W1[(32 * s2 + 8 * qq + c) * 64 + i];
            uint4 qhv, qlv;
            pack8(v, qhv, qlv);
            const int q = 4 * s2 + qq;
            const uint32_t off = (uint32_t)i * 128 + (uint32_t)((q ^ (i & 7)) << 4);
            *(uint4*)(smem + S_BHI + off) = qhv;
            *(uint4*)(smem + S_BLO + off) = qlv;
        }
    }
    __syncthreads();

    // ---- MMA: warp wid owns pixel rows [16*wid, 16*wid+16) ----
    float dacc[8][4];
    #pragma unroll
    for (int nt = 0; nt < 8; nt++)
        #pragma unroll
        for (int r = 0; r < 4; r++) dacc[nt][r] = 0.f;

    {
        const int m0w = 16 * wid;
        const int rl  = lane & 15;
        const int qhh = lane >> 4;
        const int rx  = lane & 7;

        #pragma unroll
        for (int term = 0; term < 3; term++) {
            const uint32_t SA = sb + (term == 1 ? S_ALO : S_AHI);
            const uint32_t SB = sb + (term == 2 ? S_BLO : S_BHI);
            #pragma unroll
            for (int kt = 0; kt < 4; kt++) {
                const uint32_t kx = (uint32_t)(((2 * kt + qhh) ^ rx) << 4);
                uint32_t a0[4];
                ldsm4(SA + (uint32_t)(m0w + rl) * 128 + kx, a0[0], a0[1], a0[2], a0[3]);
                // consume each B ldsm immediately (live B regs: 4, not 16)
                #pragma unroll
                for (int ntp = 0; ntp < 4; ntp++) {
                    uint32_t r0, r1, r2, r3;
                    ldsm4(SB + (uint32_t)(16 * ntp + rl) * 128 + kx, r0, r1, r2, r3);
                    mma16816(dacc[2 * ntp],     a0, r0, r2);
                    mma16816(dacc[2 * ntp + 1], a0, r1, r3);
                }
            }
        }
    }
    __syncthreads();   // all ldmatrix reads done before base_s overwrites A/B

    // ---- D fragments -> base_s[px][i] ----
    float* base_s = (float*)smem;
    {
        const int g = lane >> 2, tg = lane & 3;
        const int m = 16 * wid + g;
        #pragma unroll
        for (int nt = 0; nt < 8; nt++) {
            const int col = nt * 8 + 2 * tg;
            *(float2*)(base_s + m * BSTR + col) =
                make_float2(dacc[nt][0], dacc[nt][1]);
            *(float2*)(base_s + (m + 8) * BSTR + col) =
                make_float2(dacc[nt][2], dacc[nt][3]);
        }
    }
    __syncthreads();

    // ---- epilogue: rows j = 2s + {0,1}; tables from __constant__ ----
    const float4* brow4 = (const float4*)(base_s + px * BSTR);
    const float rj0 = -0.75f + 0.5f * (float)(2 * s);
    const float rj1 = rj0 + 0.5f;
    const ull RK01 = pk(-0.75f, -0.25f);
    const ull RK23 = pk(0.25f, 0.75f);

    ull acc[3][2][2];
    {
        const float4 bz = cET[128];
        const float bv3[3] = {bz.x, bz.y, bz.z};
        #pragma unroll
        for (int ch = 0; ch < 3; ch++) {
            const ull bv = pk(bv3[ch], bv3[ch]);
            acc[ch][0][0] = bv; acc[ch][0][1] = bv;
            acc[ch][1][0] = bv; acc[ch][1][1] = bv;
        }
    }

    #pragma unroll
    for (int i4 = 0; i4 < 16; i4++) {
        const float4 bq = brow4[i4];          // 4 base values (1 LDS.128)
        const float bsv[4] = {bq.x, bq.y, bq.z, bq.w};
        #pragma unroll
        for (int u = 0; u < 4; u++) {
            const int i = 4 * i4 + u;
            const float4 e0 = cET[2 * i];      // const port
            const float4 e1 = cET[2 * i + 1];  // const port
            const float tb = bsv[u] + e0.z;
            const float t0 = fmaf(rj0, e0.x, tb);
            const float t1 = fmaf(rj1, e0.x, tb);
            const ull vd  = pk(e0.y, e0.y);
            const ull wd0 = pk(e1.x, e1.x);
            const ull wd1 = pk(e1.y, e1.y);
            const ull wd2 = pk(e1.z, e1.z);
            #pragma unroll
            for (int jj = 0; jj < 2; jj++) {
                const float tj = jj ? t1 : t0;
                const ull td = pk(tj, tj);
                const ull h01 = relu2(fmax2p(vd, RK01, td));
                const ull h23 = relu2(fmax2p(vd, RK23, td));
                acc[0][jj][0] = fmax2p(h01, wd0, acc[0][jj][0]);
                acc[0][jj][1] = fmax2p(h23, wd0, acc[0][jj][1]);
                acc[1][jj][0] = fmax2p(h01, wd1, acc[1][jj][0]);
                acc[1][jj][1] = fmax2p(h23, wd1, acc[1][jj][1]);
                acc[2][jj][0] = fmax2p(h01, wd2, acc[2][jj][0]);
                acc[2][jj][1] = fmax2p(h23, wd2, acc[2][jj][1]);
            }
        }
    }

    // ---- stores: out[b, ch, 4h + 2s + jj, 4*px .. 4*px+3] ----
    float4* op = (float4*)out;
    #pragma unroll
    for (int ch = 0; ch < 3; ch++) {
        #pragma unroll
        for (int jj = 0; jj < 2; jj++) {
            const float2 a0 = upk(acc[ch][jj][0]);
            const float2 a1 = upk(acc[ch][jj][1]);
            const size_t idx =
                ((size_t)(b * 3 + ch) * OUT + (4 * h + 2 * s + jj)) * (OUT / 4) + px;
            op[idx] = make_float4(a0.x, a0.y, a1.x, a1.y);
        }
    }
}

}  // namespace

extern "C" void kernel_launch(void* const* d_in, const int* in_sizes, int n_in,
                              void* d_out, int out_size) {
    const float* x  = (const float*)d_in[0];
    const float* W1 = (const float*)d_in[1];
    const float* b1 = (const float*)d_in[2];
    const float* W2 = (const float*)d_in[3];
    const float* b2 = (const float*)d_in[4];
    float* out = (float*)d_out;

    prep_et<<<1, 64>>>(W1, b1, W2, b2);

    void* getp = nullptr;
    cudaGetSymbolAddress(&getp, gET);
    cudaMemcpyToSymbolAsync(cET, getp, sizeof(float4) * 129, 0,
                            cudaMemcpyDeviceToDevice, 0);

    cudaFuncSetAttribute(mlp_interp_mma,
                         cudaFuncAttributeMaxDynamicSharedMemorySize, S_TOTAL);
    mlp_interp_mma<<<512, 256, S_TOTAL>>>(x, W1, out);
}

// round 12
// speedup vs baseline: 1.1390x; 1.1390x over previous
#include <cuda_runtime.h>
#include <cuda_bf16.h>
#include <cstdint>
#include <cstring>

// MLP_Interpolate: 4x nearest upsample + 2-layer MLP.
// Base GEMM on tensor pipe via baseline-PTX mma.sync m16n8k16 bf16
// (3-term split Ah*Bh + Al*Bh + Ah*Bl, fp32 accum, residual ~1.5e-5 rel).
// 256 threads/CTA, occupancy 3 (80 regs — 64 spills, measured round 11).
// Epilogue j-split; tables in __constant__ with PRE-DUPLICATED f32x2 pairs
// (LDC.64 -> aligned register pair, no duplication MOVs, no L1 traffic).

namespace {

typedef unsigned long long ull;

__device__ __forceinline__ ull pk(float lo, float hi) {
    ull r; asm("mov.b64 %0, {%1, %2};" : "=l"(r) : "f"(lo), "f"(hi)); return r;
}
__device__ __forceinline__ float2 upk(ull a) {
    float2 r; asm("mov.b64 {%0, %1}, %2;" : "=f"(r.x), "=f"(r.y) : "l"(a)); return r;
}
__device__ __forceinline__ ull fmax2p(ull a, ull b, ull c) {
    ull d; asm("fma.rn.f32x2 %0, %1, %2, %3;" : "=l"(d) : "l"(a), "l"(b), "l"(c)); return d;
}
__device__ __forceinline__ ull relu2(ull v) {
    float2 t = upk(v);
    return pk(fmaxf(t.x, 0.f), fmaxf(t.y, 0.f));
}
__device__ __forceinline__ uint32_t s2u(const void* p) {
    uint32_t a;
    asm("{ .reg .u64 t; cvta.to.shared.u64 t, %1; cvt.u32.u64 %0, t; }" : "=r"(a) : "l"(p));
    return a;
}
__device__ __forceinline__ void ldsm4(uint32_t addr, uint32_t& r0, uint32_t& r1,
                                      uint32_t& r2, uint32_t& r3) {
    asm volatile("ldmatrix.sync.aligned.m8n8.x4.shared.b16 {%0,%1,%2,%3}, [%4];"
                 : "=r"(r0), "=r"(r1), "=r"(r2), "=r"(r3) : "r"(addr));
}
__device__ __forceinline__ void mma16816(float* d, const uint32_t* a,
                                         uint32_t b0, uint32_t b1) {
    asm volatile(
        "mma.sync.aligned.m16n8k16.row.col.f32.bf16.bf16.f32 "
        "{%0,%1,%2,%3}, {%4,%5,%6,%7}, {%8,%9}, {%0,%1,%2,%3};"
        : "+f"(d[0]), "+f"(d[1]), "+f"(d[2]), "+f"(d[3])
        : "r"(a[0]), "r"(a[1]), "r"(a[2]), "r"(a[3]), "r"(b0), "r"(b1));
}

constexpr int Hh = 128, Wd = 128, HW = Hh * Wd, OUT = 512;
constexpr int BSTR = 68;   // base_s row stride (floats); 272 B, 16B-aligned

// Pre-duplicated epilogue table entry (40 B, 8B-aligned):
//   vd  = {v_i, v_i}, wdX = {w2[i][X], w2[i][X]} duplicated f32x2 pairs
//   u = W1[64][i], b1 = b1[i]
// Entry 64 carries b2 pairs: vd={b2_0,b2_0}, wd0={b2_1,b2_1}, wd1={b2_2,b2_2}.
struct ETe { ull vd, wd0, wd1, wd2; float u, b1; };
__constant__ ETe cET2[65];
__device__   ETe gET2[65];

// smem layout (bytes); base_s (128*68*4 = 34816) overlays A/B after MMA
constexpr int S_AHI = 0;            // X_hi  [128][64 bf16]  16384
constexpr int S_ALO = 16384;        // X_lo                  16384
constexpr int S_BHI = 32768;        // W1T_hi [64][64 bf16]   8192
constexpr int S_BLO = 40960;        // W1T_lo                 8192
constexpr int S_TOTAL = 49152;

// split 8 floats -> bf16-hi quad + bf16-lo quad
__device__ __forceinline__ void pack8(const float* v, uint4& qh, uint4& ql) {
    uint32_t H[4], L[4];
    #pragma unroll
    for (int p = 0; p < 4; p++) {
        uint32_t hp;
        asm("cvt.rn.bf16x2.f32 %0, %1, %2;" : "=r"(hp) : "f"(v[2*p+1]), "f"(v[2*p]));
        const float h0 = __uint_as_float(hp << 16);
        const float h1 = __uint_as_float(hp & 0xffff0000u);
        const float l0 = v[2*p]   - h0;
        const float l1 = v[2*p+1] - h1;
        uint32_t lp;
        asm("cvt.rn.bf16x2.f32 %0, %1, %2;" : "=r"(lp) : "f"(l1), "f"(l0));
        H[p] = hp; L[p] = lp;
    }
    qh = make_uint4(H[0], H[1], H[2], H[3]);
    ql = make_uint4(L[0], L[1], L[2], L[3]);
}

__global__ void prep_et(const float* __restrict__ W1, const float* __restrict__ b1,
                        const float* __restrict__ W2, const float* __restrict__ b2)
{
    const int c = threadIdx.x;   // 64 threads
    ETe e;
    const float v = W1[64 * 64 + 64 + c];
    e.vd  = pk(v, v);
    e.wd0 = pk(W2[c * 3 + 0], W2[c * 3 + 0]);
    e.wd1 = pk(W2[c * 3 + 1], W2[c * 3 + 1]);
    e.wd2 = pk(W2[c * 3 + 2], W2[c * 3 + 2]);
    e.u   = W1[64 * 64 + c];
    e.b1  = b1[c];
    gET2[c] = e;
    if (c == 0) {
        ETe z;
        z.vd  = pk(b2[0], b2[0]);
        z.wd0 = pk(b2[1], b2[1]);
        z.wd1 = pk(b2[2], b2[2]);
        z.wd2 = 0ull; z.u = 0.f; z.b1 = 0.f;
        gET2[64] = z;
    }
}

__global__ __launch_bounds__(256, 3)
void mlp_interp_mma(const float* __restrict__ x, const float* __restrict__ W1,
                    float* __restrict__ out)
{
    extern __shared__ char smem[];
    const uint32_t sb = s2u(smem);
    const int tid  = threadIdx.x;
    const int lane = tid & 31;
    const int wid  = tid >> 5;            // 0..7
    const int px   = tid >> 1;            // pixel 0..127
    const int s    = tid & 1;             // j-half
    const int cta  = blockIdx.x;          // 512: (b, h)
    const int h = cta & (Hh - 1);
    const int b = cta >> 7;

    // ---- stage A: thread (px, s) packs channels [32s, 32s+32) of pixel px ----
    {
        const float* xp = x + ((size_t)b * 64 + 32 * s) * HW + h * Wd + px;
        #pragma unroll
        for (int qq = 0; qq < 4; qq++) {
            float v[8];
            #pragma unroll
            for (int c = 0; c < 8; c++) v[c] = xp[(size_t)(8 * qq + c) * HW];
            uint4 qhv, qlv;
            pack8(v, qhv, qlv);
            const int q = 4 * s + qq;
            const uint32_t off = (uint32_t)px * 128 + (uint32_t)((q ^ (px & 7)) << 4);
            *(uint4*)(smem + S_AHI + off) = qhv;
            *(uint4*)(smem + S_ALO + off) = qlv;
        }
    }

    if (tid >= 128) {
        // ---- stage B: thread (i, s2) packs W1[32s2..32s2+32][i] ----
        const int t2 = tid - 128;
        const int i  = t2 >> 1;
        const int s2 = t2 & 1;
        #pragma unroll
        for (int qq = 0; qq < 4; qq++) {
            float v[8];
            #pragma unroll
            for (int c = 0; c < 8; c++) v[c] = W1[(32 * s2 + 8 * qq + c) * 64 + i];
            uint4 qhv, qlv;
            pack8(v, qhv, qlv);
            const int q = 4 * s2 + qq;
            const uint32_t off = (uint32_t)i * 128 + (uint32_t)((q ^ (i & 7)) << 4);
            *(uint4*)(smem + S_BHI + off) = qhv;
            *(uint4*)(smem + S_BLO + off) = qlv;
        }
    }
    __syncthreads();

    // ---- MMA: warp wid owns pixel rows [16*wid, 16*wid+16) ----
    float dacc[8][4];
    #pragma unroll
    for (int nt = 0; nt < 8; nt++)
        #pragma unroll
        for (int r = 0; r < 4; r++) dacc[nt][r] = 0.f;

    {
        const int m0w = 16 * wid;
        const int rl  = lane & 15;
        const int qhh = lane >> 4;
        const int rx  = lane & 7;

        #pragma unroll
        for (int term = 0; term < 3; term++) {
            const uint32_t SA = sb + (term == 1 ? S_ALO : S_AHI);
            const uint32_t SB = sb + (term == 2 ? S_BLO : S_BHI);
            #pragma unroll
            for (int kt = 0; kt < 4; kt++) {
                const uint32_t kx = (uint32_t)(((2 * kt + qhh) ^ rx) << 4);
                uint32_t a0[4];
                ldsm4(SA + (uint32_t)(m0w + rl) * 128 + kx, a0[0], a0[1], a0[2], a0[3]);
                uint32_t bl0[8], bl1[8];
                #pragma unroll
                for (int ntp = 0; ntp < 4; ntp++) {
                    uint32_t r0, r1, r2, r3;
                    ldsm4(SB + (uint32_t)(16 * ntp + rl) * 128 + kx, r0, r1, r2, r3);
                    bl0[2 * ntp] = r0; bl0[2 * ntp + 1] = r1;
                    bl1[2 * ntp] = r2; bl1[2 * ntp + 1] = r3;
                }
                #pragma unroll
                for (int nt = 0; nt < 8; nt++)
                    mma16816(dacc[nt], a0, bl0[nt], bl1[nt]);
            }
        }
    }
    __syncthreads();   // all ldmatrix reads done before base_s overwrites A/B

    // ---- D fragments -> base_s[px][i] ----
    float* base_s = (float*)smem;
    {
        const int g = lane >> 2, tg = lane & 3;
        const int m = 16 * wid + g;
        #pragma unroll
        for (int nt = 0; nt < 8; nt++) {
            const int col = nt * 8 + 2 * tg;
            *(float2*)(base_s + m * BSTR + col) =
                make_float2(dacc[nt][0], dacc[nt][1]);
            *(float2*)(base_s + (m + 8) * BSTR + col) =
                make_float2(dacc[nt][2], dacc[nt][3]);
        }
    }
    __syncthreads();

    // ---- epilogue: rows j = 2s + {0,1}; pre-duplicated const tables ----
    const float4* brow4 = (const float4*)(base_s + px * BSTR);
    const float rj0 = -0.75f + 0.5f * (float)(2 * s);
    const float rj1 = rj0 + 0.5f;
    const ull RK01 = pk(-0.75f, -0.25f);
    const ull RK23 = pk(0.25f, 0.75f);

    ull acc[3][2][2];
    {
        const ull a0 = cET2[64].vd;    // {b2_0, b2_0} pre-duplicated
        const ull a1 = cET2[64].wd0;   // {b2_1, b2_1}
        const ull a2 = cET2[64].wd1;   // {b2_2, b2_2}
        acc[0][0][0] = a0; acc[0][0][1] = a0; acc[0][1][0] = a0; acc[0][1][1] = a0;
        acc[1][0][0] = a1; acc[1][0][1] = a1; acc[1][1][0] = a1; acc[1][1][1] = a1;
        acc[2][0][0] = a2; acc[2][0][1] = a2; acc[2][1][0] = a2; acc[2][1][1] = a2;
    }

    #pragma unroll
    for (int i4 = 0; i4 < 16; i4++) {
        const float4 bq = brow4[i4];          // 4 base values (1 LDS.128)
        const float bsv[4] = {bq.x, bq.y, bq.z, bq.w};
        #pragma unroll
        for (int u = 0; u < 4; u++) {
            const int i = 4 * i4 + u;
            const ETe e = cET2[i];            // const port, pairs pre-duplicated
            const float tb = bsv[u] + e.b1;
            const float t0 = fmaf(rj0, e.u, tb);
            const float t1 = fmaf(rj1, e.u, tb);
            #pragma unroll
            for (int jj = 0; jj < 2; jj++) {
                const float tj = jj ? t1 : t0;
                const ull td = pk(tj, tj);
                const ull h01 = relu2(fmax2p(e.vd, RK01, td));
                const ull h23 = relu2(fmax2p(e.vd, RK23, td));
                acc[0][jj][0] = fmax2p(h01, e.wd0, acc[0][jj][0]);
                acc[0][jj][1] = fmax2p(h23, e.wd0, acc[0][jj][1]);
                acc[1][jj][0] = fmax2p(h01, e.wd1, acc[1][jj][0]);
                acc[1][jj][1] = fmax2p(h23, e.wd1, acc[1][jj][1]);
                acc[2][jj][0] = fmax2p(h01, e.wd2, acc[2][jj][0]);
                acc[2][jj][1] = fmax2p(h23, e.wd2, acc[2][jj][1]);
            }
        }
    }

    // ---- stores: out[b, ch, 4h + 2s + jj, 4*px .. 4*px+3] ----
    float4* op = (float4*)out;
    #pragma unroll
    for (int ch = 0; ch < 3; ch++) {
        #pragma unroll
        for (int jj = 0; jj < 2; jj++) {
            const float2 a0 = upk(acc[ch][jj][0]);
            const float2 a1 = upk(acc[ch][jj][1]);
            const size_t idx =
                ((size_t)(b * 3 + ch) * OUT + (4 * h + 2 * s + jj)) * (OUT / 4) + px;
            op[idx] = make_float4(a0.x, a0.y, a1.x, a1.y);
        }
    }
}

}  // namespace

extern "C" void kernel_launch(void* const* d_in, const int* in_sizes, int n_in,
                              void* d_out, int out_size) {
    const float* x  = (const float*)d_in[0];
    const float* W1 = (const float*)d_in[1];
    const float* b1 = (const float*)d_in[2];
    const float* W2 = (const float*)d_in[3];
    const float* b2 = (const float*)d_in[4];
    float* out = (float*)d_out;

    prep_et<<<1, 64>>>(W1, b1, W2, b2);

    void* getp = nullptr;
    cudaGetSymbolAddress(&getp, gET2);
    cudaMemcpyToSymbolAsync(cET2, getp, sizeof(ETe) * 65, 0,
                            cudaMemcpyDeviceToDevice, 0);

    cudaFuncSetAttribute(mlp_interp_mma,
                         cudaFuncAttributeMaxDynamicSharedMemorySize, S_TOTAL);
    mlp_interp_mma<<<512, 256, S_TOTAL>>>(x, W1, out);
}

// round 13
// speedup vs baseline: 1.2188x; 1.0700x over previous
#include <cuda_runtime.h>
#include <cuda_bf16.h>
#include <cstdint>
#include <cstring>

// MLP_Interpolate: 4x nearest upsample + 2-layer MLP. SINGLE LAUNCH.
// Base GEMM on tensor pipe via baseline-PTX mma.sync m16n8k16 bf16
// (3-term split Ah*Bh + Al*Bh + Ah*Bl, fp32 accum, residual ~1.5e-5 rel).
// 256 threads/CTA, occupancy 3 (80 regs). Epilogue j-split; epilogue table
// computed in-CTA into smem (warp-uniform broadcast loads) — avoids the
// ~3.8us prep-kernel + memcpyToSymbol graph-node overhead measured r10/r12.

namespace {

typedef unsigned long long ull;

__device__ __forceinline__ ull pk(float lo, float hi) {
    ull r; asm("mov.b64 %0, {%1, %2};" : "=l"(r) : "f"(lo), "f"(hi)); return r;
}
__device__ __forceinline__ float2 upk(ull a) {
    float2 r; asm("mov.b64 {%0, %1}, %2;" : "=f"(r.x), "=f"(r.y) : "l"(a)); return r;
}
__device__ __forceinline__ ull fmax2p(ull a, ull b, ull c) {
    ull d; asm("fma.rn.f32x2 %0, %1, %2, %3;" : "=l"(d) : "l"(a), "l"(b), "l"(c)); return d;
}
__device__ __forceinline__ ull relu2(ull v) {
    float2 t = upk(v);
    return pk(fmaxf(t.x, 0.f), fmaxf(t.y, 0.f));
}
__device__ __forceinline__ uint32_t s2u(const void* p) {
    uint32_t a;
    asm("{ .reg .u64 t; cvta.to.shared.u64 t, %1; cvt.u32.u64 %0, t; }" : "=r"(a) : "l"(p));
    return a;
}
__device__ __forceinline__ void ldsm4(uint32_t addr, uint32_t& r0, uint32_t& r1,
                                      uint32_t& r2, uint32_t& r3) {
    asm volatile("ldmatrix.sync.aligned.m8n8.x4.shared.b16 {%0,%1,%2,%3}, [%4];"
                 : "=r"(r0), "=r"(r1), "=r"(r2), "=r"(r3) : "r"(addr));
}
__device__ __forceinline__ void mma16816(float* d, const uint32_t* a,
                                         uint32_t b0, uint32_t b1) {
    asm volatile(
        "mma.sync.aligned.m16n8k16.row.col.f32.bf16.bf16.f32 "
        "{%0,%1,%2,%3}, {%4,%5,%6,%7}, {%8,%9}, {%0,%1,%2,%3};"
        : "+f"(d[0]), "+f"(d[1]), "+f"(d[2]), "+f"(d[3])
        : "r"(a[0]), "r"(a[1]), "r"(a[2]), "r"(a[3]), "r"(b0), "r"(b1));
}

constexpr int Hh = 128, Wd = 128, HW = Hh * Wd, OUT = 512;
constexpr int BSTR = 68;   // base_s row stride (floats); 272 B, 16B-aligned

// smem layout (bytes); base_s (128*68*4 = 34816) overlays A/B after MMA.
// ET lives ABOVE the overlay region and survives.
constexpr int S_AHI = 0;            // X_hi  [128][64 bf16]  16384
constexpr int S_ALO = 16384;        // X_lo                  16384
constexpr int S_BHI = 32768;        // W1T_hi [64][64 bf16]   8192
constexpr int S_BLO = 40960;        // W1T_lo                 8192
constexpr int S_ET  = 49152;        // ET4[128] float4        2048
constexpr int S_B2  = S_ET + 2048;  // b2[4]                    16
constexpr int S_TOTAL = S_B2 + 16;  // 51216

// split 8 floats -> bf16-hi quad + bf16-lo quad
__device__ __forceinline__ void pack8(const float* v, uint4& qh, uint4& ql) {
    uint32_t H[4], L[4];
    #pragma unroll
    for (int p = 0; p < 4; p++) {
        uint32_t hp;
        asm("cvt.rn.bf16x2.f32 %0, %1, %2;" : "=r"(hp) : "f"(v[2*p+1]), "f"(v[2*p]));
        const float h0 = __uint_as_float(hp << 16);
        const float h1 = __uint_as_float(hp & 0xffff0000u);
        const float l0 = v[2*p]   - h0;
        const float l1 = v[2*p+1] - h1;
        uint32_t lp;
        asm("cvt.rn.bf16x2.f32 %0, %1, %2;" : "=r"(lp) : "f"(l1), "f"(l0));
        H[p] = hp; L[p] = lp;
    }
    qh = make_uint4(H[0], H[1], H[2], H[3]);
    ql = make_uint4(L[0], L[1], L[2], L[3]);
}

__global__ __launch_bounds__(256, 3)
void mlp_interp_mma(const float* __restrict__ x, const float* __restrict__ W1,
                    const float* __restrict__ b1, const float* __restrict__ W2,
                    const float* __restrict__ b2, float* __restrict__ out)
{
    extern __shared__ char smem[];
    const uint32_t sb = s2u(smem);
    const int tid  = threadIdx.x;
    const int lane = tid & 31;
    const int wid  = tid >> 5;            // 0..7
    const int px   = tid >> 1;            // pixel 0..127
    const int s    = tid & 1;             // j-half
    const int cta  = blockIdx.x;          // 512: (b, h)
    const int h = cta & (Hh - 1);
    const int b = cta >> 7;

    // ---- stage A: thread (px, s) packs channels [32s, 32s+32) of pixel px ----
    {
        const float* xp = x + ((size_t)b * 64 + 32 * s) * HW + h * Wd + px;
        #pragma unroll
        for (int qq = 0; qq < 4; qq++) {
            float v[8];
            #pragma unroll
            for (int c = 0; c < 8; c++) v[c] = xp[(size_t)(8 * qq + c) * HW];
            uint4 qhv, qlv;
            pack8(v, qhv, qlv);
            const int q = 4 * s + qq;
            const uint32_t off = (uint32_t)px * 128 + (uint32_t)((q ^ (px & 7)) << 4);
            *(uint4*)(smem + S_AHI + off) = qhv;
            *(uint4*)(smem + S_ALO + off) = qlv;
        }
    }

    if (tid >= 128) {
        // ---- stage B: thread (i, s2) packs W1[32s2..32s2+32][i] ----
        const int t2 = tid - 128;
        const int i  = t2 >> 1;
        const int s2 = t2 & 1;
        #pragma unroll
        for (int qq = 0; qq < 4; qq++) {
            float v[8];
            #pragma unroll
            for (int c = 0; c < 8; c++) v[c] = W1[(32 * s2 + 8 * qq + c) * 64 + i];
            uint4 qhv, qlv;
            pack8(v, qhv, qlv);
            const int q = 4 * s2 + qq;
            const uint32_t off = (uint32_t)i * 128 + (uint32_t)((q ^ (i & 7)) << 4);
            *(uint4*)(smem + S_BHI + off) = qhv;
            *(uint4*)(smem + S_BLO + off) = qlv;
        }
    } else if (tid < 64) {
        // ---- epilogue table in smem (tiny: ~20 instrs on 64 threads) ----
        const int c = tid;
        float4* ET4 = (float4*)(smem + S_ET);
        ET4[2 * c]     = make_float4(W1[64 * 64 + c], W1[64 * 64 + 64 + c],
                                     b1[c], 0.f);
        ET4[2 * c + 1] = make_float4(W2[c * 3 + 0], W2[c * 3 + 1],
                                     W2[c * 3 + 2], 0.f);
        if (c < 3) ((float*)(smem + S_B2))[c] = b2[c];
    }
    __syncthreads();

    // ---- MMA: warp wid owns pixel rows [16*wid, 16*wid+16) ----
    float dacc[8][4];
    #pragma unroll
    for (int nt = 0; nt < 8; nt++)
        #pragma unroll
        for (int r = 0; r < 4; r++) dacc[nt][r] = 0.f;

    {
        const int m0w = 16 * wid;
        const int rl  = lane & 15;
        const int qhh = lane >> 4;
        const int rx  = lane & 7;

        #pragma unroll
        for (int term = 0; term < 3; term++) {
            const uint32_t SA = sb + (term == 1 ? S_ALO : S_AHI);
            const uint32_t SB = sb + (term == 2 ? S_BLO : S_BHI);
            #pragma unroll
            for (int kt = 0; kt < 4; kt++) {
                const uint32_t kx = (uint32_t)(((2 * kt + qhh) ^ rx) << 4);
                uint32_t a0[4];
                ldsm4(SA + (uint32_t)(m0w + rl) * 128 + kx, a0[0], a0[1], a0[2], a0[3]);
                // consume each B ldsm immediately (low live-register count)
                #pragma unroll
                for (int ntp = 0; ntp < 4; ntp++) {
                    uint32_t r0, r1, r2, r3;
                    ldsm4(SB + (uint32_t)(16 * ntp + rl) * 128 + kx, r0, r1, r2, r3);
                    mma16816(dacc[2 * ntp],     a0, r0, r2);
                    mma16816(dacc[2 * ntp + 1], a0, r1, r3);
                }
            }
        }
    }
    __syncthreads();   // all ldmatrix reads done before base_s overwrites A/B

    // ---- D fragments -> base_s[px][i] ----
    float* base_s = (float*)smem;
    {
        const int g = lane >> 2, tg = lane & 3;
        const int m = 16 * wid + g;
        #pragma unroll
        for (int nt = 0; nt < 8; nt++) {
            const int col = nt * 8 + 2 * tg;
            *(float2*)(base_s + m * BSTR + col) =
                make_float2(dacc[nt][0], dacc[nt][1]);
            *(float2*)(base_s + (m + 8) * BSTR + col) =
                make_float2(dacc[nt][2], dacc[nt][3]);
        }
    }
    __syncthreads();

    // ---- epilogue: rows j = 2s + {0,1}; tables via broadcast LDS ----
    const float4* ET4 = (const float4*)(smem + S_ET);
    const float*  b2s = (const float*)(smem + S_B2);
    const float4* brow4 = (const float4*)(base_s + px * BSTR);
    const float rj0 = -0.75f + 0.5f * (float)(2 * s);
    const float rj1 = rj0 + 0.5f;
    const ull RK01 = pk(-0.75f, -0.25f);
    const ull RK23 = pk(0.25f, 0.75f);

    ull acc[3][2][2];
    #pragma unroll
    for (int ch = 0; ch < 3; ch++) {
        const ull bv = pk(b2s[ch], b2s[ch]);
        acc[ch][0][0] = bv; acc[ch][0][1] = bv;
        acc[ch][1][0] = bv; acc[ch][1][1] = bv;
    }

    #pragma unroll
    for (int i4 = 0; i4 < 16; i4++) {
        const float4 bq = brow4[i4];          // 4 base values (1 LDS.128)
        const float bsv[4] = {bq.x, bq.y, bq.z, bq.w};
        #pragma unroll
        for (int u = 0; u < 4; u++) {
            const int i = 4 * i4 + u;
            const float4 e0 = ET4[2 * i];      // broadcast (1 wavefront)
            const float4 e1 = ET4[2 * i + 1];  // broadcast
            const float tb = bsv[u] + e0.z;
            const float t0 = fmaf(rj0, e0.x, tb);
            const float t1 = fmaf(rj1, e0.x, tb);
            const ull vd  = pk(e0.y, e0.y);
            const ull wd0 = pk(e1.x, e1.x);
            const ull wd1 = pk(e1.y, e1.y);
            const ull wd2 = pk(e1.z, e1.z);
            #pragma unroll
            for (int jj = 0; jj < 2; jj++) {
                const float tj = jj ? t1 : t0;
                const ull td = pk(tj, tj);
                const ull h01 = relu2(fmax2p(vd, RK01, td));
                const ull h23 = relu2(fmax2p(vd, RK23, td));
                acc[0][jj][0] = fmax2p(h01, wd0, acc[0][jj][0]);
                acc[0][jj][1] = fmax2p(h23, wd0, acc[0][jj][1]);
                acc[1][jj][0] = fmax2p(h01, wd1, acc[1][jj][0]);
                acc[1][jj][1] = fmax2p(h23, wd1, acc[1][jj][1]);
                acc[2][jj][0] = fmax2p(h01, wd2, acc[2][jj][0]);
                acc[2][jj][1] = fmax2p(h23, wd2, acc[2][jj][1]);
            }
        }
    }

    // ---- stores: out[b, ch, 4h + 2s + jj, 4*px .. 4*px+3] ----
    float4* op = (float4*)out;
    #pragma unroll
    for (int ch = 0; ch < 3; ch++) {
        #pragma unroll
        for (int jj = 0; jj < 2; jj++) {
            const float2 a0 = upk(acc[ch][jj][0]);
            const float2 a1 = upk(acc[ch][jj][1]);
            const size_t idx =
                ((size_t)(b * 3 + ch) * OUT + (4 * h + 2 * s + jj)) * (OUT / 4) + px;
            op[idx] = make_float4(a0.x, a0.y, a1.x, a1.y);
        }
    }
}

}  // namespace

extern "C" void kernel_launch(void* const* d_in, const int* in_sizes, int n_in,
                              void* d_out, int out_size) {
    const float* x  = (const float*)d_in[0];
    const float* W1 = (const float*)d_in[1];
    const float* b1 = (const float*)d_in[2];
    const float* W2 = (const float*)d_in[3];
    const float* b2 = (const float*)d_in[4];
    float* out = (float*)d_out;

    cudaFuncSetAttribute(mlp_interp_mma,
                         cudaFuncAttributeMaxDynamicSharedMemorySize, S_TOTAL);
    mlp_interp_mma<<<512, 256, S_TOTAL>>>(x, W1, b1, W2, b2, out);
}

// round 14
// speedup vs baseline: 1.2484x; 1.0243x over previous
#include <cuda_runtime.h>
#include <cuda_bf16.h>
#include <cstdint>
#include <cstring>

// MLP_Interpolate: 4x nearest upsample + 2-layer MLP. SINGLE LAUNCH.
// GEMM1 (base = X @ W1[0:64]^T): tensor pipe, bf16 3-term split (~1.5e-5).
// GEMM2 (out = relu(H) @ W2): tensor pipe, fp16 single-term (~2e-4), H built
// directly in mma A-fragment layout from the smem base tile + per-thread
// ajbk constants (rel_j*u + rel_k*v + b1). Scalar-pipe fma per thread drops
// ~1150 -> ~330; second layer rides the (previously 10%-busy) tensor pipe.

namespace {

typedef unsigned long long ull;

__device__ __forceinline__ ull pk(float lo, float hi) {
    ull r; asm("mov.b64 %0, {%1, %2};" : "=l"(r) : "f"(lo), "f"(hi)); return r;
}
__device__ __forceinline__ float2 upk(ull a) {
    float2 r; asm("mov.b64 {%0, %1}, %2;" : "=f"(r.x), "=f"(r.y) : "l"(a)); return r;
}
__device__ __forceinline__ ull addx2(ull a, ull b) {
    ull d; asm("add.rn.f32x2 %0, %1, %2;" : "=l"(d) : "l"(a), "l"(b)); return d;
}
__device__ __forceinline__ uint32_t s2u(const void* p) {
    uint32_t a;
    asm("{ .reg .u64 t; cvta.to.shared.u64 t, %1; cvt.u32.u64 %0, t; }" : "=r"(a) : "l"(p));
    return a;
}
// f32x2 pair -> relu'd f16x2 (low element = low half)
__device__ __forceinline__ uint32_t cvt_relu_f16x2(ull t) {
    const float2 v = upk(t);
    uint32_t r;
    asm("cvt.rn.f16x2.f32 %0, %1, %2;" : "=r"(r) : "f"(v.y), "f"(v.x));
    asm("max.f16x2 %0, %0, %1;" : "+r"(r) : "r"(0u));
    return r;
}
__device__ __forceinline__ void ldsm4(uint32_t addr, uint32_t& r0, uint32_t& r1,
                                      uint32_t& r2, uint32_t& r3) {
    asm volatile("ldmatrix.sync.aligned.m8n8.x4.shared.b16 {%0,%1,%2,%3}, [%4];"
                 : "=r"(r0), "=r"(r1), "=r"(r2), "=r"(r3) : "r"(addr));
}
__device__ __forceinline__ void mma_bf16(float* d, const uint32_t* a,
                                         uint32_t b0, uint32_t b1) {
    asm volatile(
        "mma.sync.aligned.m16n8k16.row.col.f32.bf16.bf16.f32 "
        "{%0,%1,%2,%3}, {%4,%5,%6,%7}, {%8,%9}, {%0,%1,%2,%3};"
        : "+f"(d[0]), "+f"(d[1]), "+f"(d[2]), "+f"(d[3])
        : "r"(a[0]), "r"(a[1]), "r"(a[2]), "r"(a[3]), "r"(b0), "r"(b1));
}
__device__ __forceinline__ void mma_f16(float* d, const uint32_t* a,
                                        uint32_t b0, uint32_t b1) {
    asm volatile(
        "mma.sync.aligned.m16n8k16.row.col.f32.f16.f16.f32 "
        "{%0,%1,%2,%3}, {%4,%5,%6,%7}, {%8,%9}, {%0,%1,%2,%3};"
        : "+f"(d[0]), "+f"(d[1]), "+f"(d[2]), "+f"(d[3])
        : "r"(a[0]), "r"(a[1]), "r"(a[2]), "r"(a[3]), "r"(b0), "r"(b1));
}

constexpr int Hh = 128, Wd = 128, HW = Hh * Wd, OUT = 512;
constexpr int BSTR = 68;   // base_s row stride (floats); 272 B

// smem layout (bytes); base_s (128*68*4 = 34816) overlays A/B after GEMM1.
constexpr int S_AHI = 0;            // X_hi  [128][64 bf16]  16384
constexpr int S_ALO = 16384;        // X_lo                  16384
constexpr int S_BHI = 32768;        // W1T_hi [64][64 bf16]   8192
constexpr int S_BLO = 40960;        // W1T_lo                 8192
constexpr int S_ET  = 49152;        // ET4[64] float4 {u,v,b1,0}  1024
constexpr int S_TOTAL = S_ET + 1024;

// split 8 floats -> bf16-hi quad + bf16-lo quad
__device__ __forceinline__ void pack8(const float* v, uint4& qh, uint4& ql) {
    uint32_t H[4], L[4];
    #pragma unroll
    for (int p = 0; p < 4; p++) {
        uint32_t hp;
        asm("cvt.rn.bf16x2.f32 %0, %1, %2;" : "=r"(hp) : "f"(v[2*p+1]), "f"(v[2*p]));
        const float h0 = __uint_as_float(hp << 16);
        const float h1 = __uint_as_float(hp & 0xffff0000u);
        const float l0 = v[2*p]   - h0;
        const float l1 = v[2*p+1] - h1;
        uint32_t lp;
        asm("cvt.rn.bf16x2.f32 %0, %1, %2;" : "=r"(lp) : "f"(l1), "f"(l0));
        H[p] = hp; L[p] = lp;
    }
    qh = make_uint4(H[0], H[1], H[2], H[3]);
    ql = make_uint4(L[0], L[1], L[2], L[3]);
}

__global__ __launch_bounds__(256, 3)
void mlp_interp_mma(const float* __restrict__ x, const float* __restrict__ W1,
                    const float* __restrict__ b1, const float* __restrict__ W2,
                    const float* __restrict__ b2, float* __restrict__ out)
{
    extern __shared__ char smem[];
    const uint32_t sb = s2u(smem);
    const int tid  = threadIdx.x;
    const int lane = tid & 31;
    const int wid  = tid >> 5;            // 0..7
    const int pxs  = tid >> 1;            // staging pixel 0..127
    const int shalf = tid & 1;            // staging channel half
    const int cta  = blockIdx.x;          // 512: (b, h)
    const int h = cta & (Hh - 1);
    const int b = cta >> 7;

    // ---- stage A: thread (pxs, shalf) packs channels [32s, 32s+32) ----
    {
        const float* xp = x + ((size_t)b * 64 + 32 * shalf) * HW + h * Wd + pxs;
        #pragma unroll
        for (int qq = 0; qq < 4; qq++) {
            float v[8];
            #pragma unroll
            for (int c = 0; c < 8; c++) v[c] = xp[(size_t)(8 * qq + c) * HW];
            uint4 qhv, qlv;
            pack8(v, qhv, qlv);
            const int q = 4 * shalf + qq;
            const uint32_t off = (uint32_t)pxs * 128 + (uint32_t)((q ^ (pxs & 7)) << 4);
            *(uint4*)(smem + S_AHI + off) = qhv;
            *(uint4*)(smem + S_ALO + off) = qlv;
        }
    }

    if (tid >= 128) {
        // ---- stage B: thread (i, s2) packs W1[32s2..32s2+32][i] ----
        const int t2 = tid - 128;
        const int i  = t2 >> 1;
        const int s2 = t2 & 1;
        #pragma unroll
        for (int qq = 0; qq < 4; qq++) {
            float v[8];
            #pragma unroll
            for (int c = 0; c < 8; c++) v[c] = W1[(32 * s2 + 8 * qq + c) * 64 + i];
            uint4 qhv, qlv;
            pack8(v, qhv, qlv);
            const int q = 4 * s2 + qq;
            const uint32_t off = (uint32_t)i * 128 + (uint32_t)((q ^ (i & 7)) << 4);
            *(uint4*)(smem + S_BHI + off) = qhv;
            *(uint4*)(smem + S_BLO + off) = qlv;
        }
    } else if (tid < 64) {
        // ---- ET table: {u_i, v_i, b1_i, 0} ----
        const int c = tid;
        ((float4*)(smem + S_ET))[c] =
            make_float4(W1[64 * 64 + c], W1[64 * 64 + 64 + c], b1[c], 0.f);
    }
    __syncthreads();

    // ---- GEMM1: warp wid owns pixel rows [16*wid, 16*wid+16) ----
    float dacc[8][4];
    #pragma unroll
    for (int nt = 0; nt < 8; nt++)
        #pragma unroll
        for (int r = 0; r < 4; r++) dacc[nt][r] = 0.f;

    {
        const int m0w = 16 * wid;
        const int rl  = lane & 15;
        const int qhh = lane >> 4;
        const int rx  = lane & 7;

        #pragma unroll
        for (int term = 0; term < 3; term++) {
            const uint32_t SA = sb + (term == 1 ? S_ALO : S_AHI);
            const uint32_t SB = sb + (term == 2 ? S_BLO : S_BHI);
            #pragma unroll
            for (int kt = 0; kt < 4; kt++) {
                const uint32_t kx = (uint32_t)(((2 * kt + qhh) ^ rx) << 4);
                uint32_t a0[4];
                ldsm4(SA + (uint32_t)(m0w + rl) * 128 + kx, a0[0], a0[1], a0[2], a0[3]);
                #pragma unroll
                for (int ntp = 0; ntp < 4; ntp++) {
                    uint32_t r0, r1, r2, r3;
                    ldsm4(SB + (uint32_t)(16 * ntp + rl) * 128 + kx, r0, r1, r2, r3);
                    mma_bf16(dacc[2 * ntp],     a0, r0, r2);
                    mma_bf16(dacc[2 * ntp + 1], a0, r1, r3);
                }
            }
        }
    }
    __syncthreads();   // all ldmatrix reads done before base_s overwrites A/B

    // ---- D fragments -> base_s[px][i] ----
    float* base_s = (float*)smem;
    {
        const int g = lane >> 2, tg0 = lane & 3;
        const int m = 16 * wid + g;
        #pragma unroll
        for (int nt = 0; nt < 8; nt++) {
            const int col = nt * 8 + 2 * tg0;
            *(float2*)(base_s + m * BSTR + col) =
                make_float2(dacc[nt][0], dacc[nt][1]);
            *(float2*)(base_s + (m + 8) * BSTR + col) =
                make_float2(dacc[nt][2], dacc[nt][3]);
        }
    }
    __syncthreads();

    // ==== GEMM2 epilogue: per px, out[16 jk, 8ch] = relu(H)[16,64] @ W2 ====
    const int tg   = lane & 3;
    const int row0 = lane >> 2;            // jk row (j = row>>2, k = row&3)
    const int j0   = row0 >> 2;
    const int k0i  = row0 & 3;
    const float rj = -0.75f + 0.5f * (float)j0;
    const float rk = -0.75f + 0.5f * (float)k0i;

    // per-thread ajbk constants for my 16 i-cols (pairs), rows row0 / row0+8
    const float4* ET4 = (const float4*)(smem + S_ET);
    ull ajbk0[8], ajbk1[8];
    #pragma unroll
    for (int p = 0; p < 8; p++) {
        const int i0 = (p >> 1) * 16 + (p & 1) * 8 + 2 * tg;
        const float4 ea = ET4[i0];
        const float4 eb = ET4[i0 + 1];
        const float f0 = fmaf(rj, ea.x, fmaf(rk, ea.y, ea.z));
        const float f1 = fmaf(rj, eb.x, fmaf(rk, eb.y, eb.z));
        ajbk0[p] = pk(f0, f1);                       // row0
        ajbk1[p] = pk(f0 + ea.x, f1 + eb.x);         // row0+8 (j+2 -> rel+1)
    }

    // W2 fp16 B-fragments (col n = lane>>2; valid n < 3)
    const int nn = lane >> 2;
    const bool nv = nn < 3;
    uint32_t bw[4][2];
    #pragma unroll
    for (int kt = 0; kt < 4; kt++) {
        #pragma unroll
        for (int hh = 0; hh < 2; hh++) {
            const int kk = kt * 16 + 2 * tg + hh * 8;
            const float w0 = nv ? W2[kk * 3 + nn] : 0.f;
            const float w1 = nv ? W2[(kk + 1) * 3 + nn] : 0.f;
            asm("cvt.rn.f16x2.f32 %0, %1, %2;" : "=r"(bw[kt][hh]) : "f"(w1), "f"(w0));
        }
    }

    const int ch0 = 2 * tg, ch1 = 2 * tg + 1;
    const float bb0 = (ch0 < 3) ? b2[ch0] : 0.f;
    const float bb1 = (ch1 < 3) ? b2[ch1] : 0.f;

    #pragma unroll 2
    for (int t16 = 0; t16 < 16; t16++) {
        const int px = 16 * wid + t16;
        const ull* bprow = (const ull*)(base_s + px * BSTR);
        float C[4] = {0.f, 0.f, 0.f, 0.f};
        #pragma unroll
        for (int kt = 0; kt < 4; kt++) {
            uint32_t a[4];
            {
                const ull bp = bprow[kt * 8 + tg];
                a[0] = cvt_relu_f16x2(addx2(bp, ajbk0[kt * 2]));
                a[1] = cvt_relu_f16x2(addx2(bp, ajbk1[kt * 2]));
            }
            {
                const ull bp = bprow[kt * 8 + 4 + tg];
                a[2] = cvt_relu_f16x2(addx2(bp, ajbk0[kt * 2 + 1]));
                a[3] = cvt_relu_f16x2(addx2(bp, ajbk1[kt * 2 + 1]));
            }
            mma_f16(C, a, bw[kt][0], bw[kt][1]);
        }
        // stores: rows (j0, k0i) and (j0+2, k0i); cols ch0, ch1
        const int xx = 4 * px + k0i;
        if (ch0 < 3) {
            out[((size_t)(b * 3 + ch0) * OUT + 4 * h + j0) * OUT + xx]       = C[0] + bb0;
            out[((size_t)(b * 3 + ch0) * OUT + 4 * h + j0 + 2) * OUT + xx]   = C[2] + bb0;
        }
        if (ch1 < 3) {
            out[((size_t)(b * 3 + ch1) * OUT + 4 * h + j0) * OUT + xx]       = C[1] + bb1;
            out[((size_t)(b * 3 + ch1) * OUT + 4 * h + j0 + 2) * OUT + xx]   = C[3] + bb1;
        }
    }
}

}  // namespace

extern "C" void kernel_launch(void* const* d_in, const int* in_sizes, int n_in,
                              void* d_out, int out_size) {
    const float* x  = (const float*)d_in[0];
    const float* W1 = (const float*)d_in[1];
    const float* b1 = (const float*)d_in[2];
    const float* W2 = (const float*)d_in[3];
    const float* b2 = (const float*)d_in[4];
    float* out = (float*)d_out;

    cudaFuncSetAttribute(mlp_interp_mma,
                         cudaFuncAttributeMaxDynamicSharedMemorySize, S_TOTAL);
    mlp_interp_mma<<<512, 256, S_TOTAL>>>(x, W1, b1, W2, b2, out);
}